// round 1
// baseline (speedup 1.0000x reference)
#include <cuda_runtime.h>
#include <cstdint>

// ---------------------------------------------------------------------------
// Protein graph featurization:
//   h_V    = LN(node_rbf(96) @ node_W^T + node_b)            [N,128]
//   h_E_in = LN(edge_feats(268) @ edge_W^T + edge_b)          [E,128]
//   h_E_ex = same for second edge list                        [E,128]
// Output layout: [h_V | h_E_in | h_E_ex] flattened fp32.
// ---------------------------------------------------------------------------

#define QMAX 131072
__device__ float g_Q[QMAX * 9];   // per-node frame: b1(3), n0(3), b2(3)

__device__ __constant__ int c_NA[6]  = {1, 1, 1, 0, 0, 3};
__device__ __constant__ int c_NB[6]  = {0, 2, 3, 2, 3, 2};
__device__ __constant__ int c_EA[16] = {1,1,2,1,0,1,3,2,2,0,2,3,0,0,3,3};
__device__ __constant__ int c_EB[16] = {1,2,1,0,1,3,1,2,0,2,3,2,0,3,0,3};
__device__ __constant__ int c_AMAP[4] = {1, 0, 2, 3};

// --------------------------- frame precompute ------------------------------
__global__ void q_kernel(const float* __restrict__ X, int N) {
    int i = blockIdx.x * blockDim.x + threadIdx.x;
    if (i >= N) return;
    float* q = &g_Q[i * 9];
    if (i == N - 1) {
        #pragma unroll
        for (int j = 0; j < 9; j++) q[j] = 0.f;
        return;
    }
    const float* x = X + (size_t)i * 12;
    float x0x = x[0], x0y = x[1], x0z = x[2];
    float x1x = x[3], x1y = x[4], x1z = x[5];
    float x2x = x[6], x2y = x[7], x2z = x[8];

    // u0 = normalize(X[i,1]-X[i,0]); u1 = normalize(X[i,2]-X[i,1])
    float ax = x1x - x0x, ay = x1y - x0y, az = x1z - x0z;
    float n = sqrtf(ax * ax + ay * ay + az * az); if (n == 0.f) n = 1.f;
    float r = 1.f / n;
    float u0x = ax * r, u0y = ay * r, u0z = az * r;

    float bx = x2x - x1x, by = x2y - x1y, bz = x2z - x1z;
    n = sqrtf(bx * bx + by * by + bz * bz); if (n == 0.f) n = 1.f;
    r = 1.f / n;
    float u1x = bx * r, u1y = by * r, u1z = bz * r;

    // n0 = normalize(cross(u0,u1))
    float cx = u0y * u1z - u0z * u1y;
    float cy = u0z * u1x - u0x * u1z;
    float cz = u0x * u1y - u0y * u1x;
    n = sqrtf(cx * cx + cy * cy + cz * cz); if (n == 0.f) n = 1.f;
    r = 1.f / n;
    float n0x = cx * r, n0y = cy * r, n0z = cz * r;

    // b1 = normalize(u0-u1)
    float dx = u0x - u1x, dy = u0y - u1y, dz = u0z - u1z;
    n = sqrtf(dx * dx + dy * dy + dz * dz); if (n == 0.f) n = 1.f;
    r = 1.f / n;
    float b1x = dx * r, b1y = dy * r, b1z = dz * r;

    // b2 = cross(b1, n0)  (not normalized)
    float b2x = b1y * n0z - b1z * n0y;
    float b2y = b1z * n0x - b1x * n0z;
    float b2z = b1x * n0y - b1y * n0x;

    q[0] = b1x; q[1] = b1y; q[2] = b1z;
    q[3] = n0x; q[4] = n0y; q[5] = n0z;
    q[6] = b2x; q[7] = b2y; q[8] = b2z;
}

// ------------------------------ node kernel --------------------------------
// 128 threads/block. W (128x96) staged in SMEM as [f][o]. One node at a time.
#define NODE_SMEM_FLOATS (96 * 128 + 96 + 12 + 8)

__global__ __launch_bounds__(128) void node_kernel(
    const float* __restrict__ X, const float* __restrict__ W,
    const float* __restrict__ b, const float* __restrict__ gain,
    const float* __restrict__ bias, float* __restrict__ out, int N)
{
    extern __shared__ float sm[];
    float* Wsh  = sm;              // 96*128
    float* feat = Wsh + 96 * 128;  // 96
    float* xsh  = feat + 96;       // 12
    float* red  = xsh + 12;        // 8

    int t = threadIdx.x;
    for (int i = t; i < 96 * 128; i += 128) {
        int o = i / 96, f = i - o * 96;
        Wsh[f * 128 + o] = W[i];
    }
    float nb = b[t], ng = gain[t], nbi = bias[t];
    __syncthreads();

    for (int i = blockIdx.x; i < N; i += gridDim.x) {
        if (t < 12) xsh[t] = X[(size_t)i * 12 + t];
        __syncthreads();
        if (t < 96) {
            int p = t >> 4, k = t & 15;
            int a = c_NA[p], bb = c_NB[p];
            float dx = xsh[a * 3 + 0] - xsh[bb * 3 + 0];
            float dy = xsh[a * 3 + 1] - xsh[bb * 3 + 1];
            float dz = xsh[a * 3 + 2] - xsh[bb * 3 + 2];
            float D = sqrtf(dx * dx + dy * dy + dz * dz + 1e-6f);
            float z = (D - (float)k * (20.f / 15.f)) * 0.8f;   // /1.25
            feat[t] = __expf(-z * z);
        }
        __syncthreads();

        float acc = nb;
        #pragma unroll 8
        for (int f = 0; f < 96; f++) acc += feat[f] * Wsh[f * 128 + t];

        float s = acc, sq = acc * acc;
        #pragma unroll
        for (int off = 16; off; off >>= 1) {
            s  += __shfl_down_sync(0xffffffffu, s, off);
            sq += __shfl_down_sync(0xffffffffu, sq, off);
        }
        if ((t & 31) == 0) { red[(t >> 5) * 2] = s; red[(t >> 5) * 2 + 1] = sq; }
        __syncthreads();
        float S  = red[0] + red[2] + red[4] + red[6];
        float Sq = red[1] + red[3] + red[5] + red[7];
        float mu = S * (1.f / 128.f);
        float var = (Sq - S * mu) * (1.f / 127.f);
        float sig = sqrtf(var + 1e-6f);
        out[(size_t)i * 128 + t] = ng * (acc - mu) / (sig + 1e-6f) + nbi;
        __syncthreads();   // red/feat/xsh reuse
    }
}

// ------------------------------ edge kernel --------------------------------
// 512 threads, 1 CTA/SM (SMEM ~210KB). edge_W resident in SMEM, float4-packed
// as Wq[f/4][o]. TILE=64 edges: gather -> RBF/orientation feats in SMEM ->
// each 128-thread group register-tiles 4 edges x 1 output -> layernorm.
#define ETILE 64
#define EK_THREADS 512
#define EDGE_SMEM_FLOATS (67 * 128 * 4 + ETILE * 268 + ETILE * 12 + ETILE * 12 + ETILE * 9 + 128)

__global__ __launch_bounds__(EK_THREADS, 1) void edge_kernel(
    const float* __restrict__ X, const int* __restrict__ idx, int E,
    const float* __restrict__ W, const float* __restrict__ b,
    const float* __restrict__ gain, const float* __restrict__ bias,
    float* __restrict__ out)
{
    extern __shared__ float sm[];
    float* Wsh    = sm;                         // 67*128*4 = 34304 floats
    float* featsh = Wsh + 67 * 128 * 4;         // 64*268 = 17152
    float* xs     = featsh + ETILE * 268;       // 768
    float* xd     = xs + ETILE * 12;            // 768
    float* qs     = xd + ETILE * 12;            // 576
    float* red    = qs + ETILE * 9;             // 128

    int t = threadIdx.x;
    // pack W: gmem [o][f] -> smem float4 blocks [f/4][o]
    for (int i = t; i < 128 * 268; i += EK_THREADS) {
        int o = i / 268, f = i - o * 268;
        Wsh[((f >> 2) * 128 + o) * 4 + (f & 3)] = W[i];
    }
    int o = t & 127;
    int g = t >> 7;                              // group 0..3 (16 edges each)
    float ebv = b[o], egv = gain[o], ebi = bias[o];

    int ntiles = (E + ETILE - 1) / ETILE;
    for (int tile = blockIdx.x; tile < ntiles; tile += gridDim.x) {
        int e0 = tile * ETILE;
        int ne = min(ETILE, E - e0);
        __syncthreads();   // protect smem reuse across tiles

        // gather X[src], X[dst], Q[src]
        for (int i = t; i < ne * 33; i += EK_THREADS) {
            int e = i / 33, j = i - e * 33;
            if (j < 12) {
                int src = idx[e0 + e];
                xs[e * 12 + j] = X[(size_t)src * 12 + j];
            } else if (j < 24) {
                int dst = idx[E + e0 + e];
                xd[e * 12 + (j - 12)] = X[(size_t)dst * 12 + (j - 12)];
            } else {
                int src = idx[e0 + e];
                qs[e * 9 + (j - 24)] = g_Q[src * 9 + (j - 24)];
            }
        }
        __syncthreads();

        // 16 pairwise distances -> 256 RBF features
        for (int i = t; i < ne * 16; i += EK_THREADS) {
            int e = i >> 4, p = i & 15;
            int a = c_EA[p], bb = c_EB[p];
            float dx = xs[e * 12 + a * 3 + 0] - xd[e * 12 + bb * 3 + 0];
            float dy = xs[e * 12 + a * 3 + 1] - xd[e * 12 + bb * 3 + 1];
            float dz = xs[e * 12 + a * 3 + 2] - xd[e * 12 + bb * 3 + 2];
            float D = sqrtf(dx * dx + dy * dy + dz * dz + 1e-6f);
            float* fr = &featsh[e * 268 + p * 16];
            #pragma unroll
            for (int k = 0; k < 16; k++) {
                float z = (D - (float)k * (20.f / 15.f)) * 0.8f;
                fr[k] = __expf(-z * z);
            }
        }
        // orientation features (12)
        for (int i = t; i < ne * 4; i += EK_THREADS) {
            int e = i >> 2, a = i & 3;
            int da = c_AMAP[a];
            float px = xd[e * 12 + da * 3 + 0] - xs[e * 12 + 0];
            float py = xd[e * 12 + da * 3 + 1] - xs[e * 12 + 1];
            float pz = xd[e * 12 + da * 3 + 2] - xs[e * 12 + 2];
            const float* q = &qs[e * 9];
            float vx = q[0] * px + q[3] * py + q[6] * pz;
            float vy = q[1] * px + q[4] * py + q[7] * pz;
            float vz = q[2] * px + q[5] * py + q[8] * pz;
            float n = sqrtf(vx * vx + vy * vy + vz * vz);
            if (n == 0.f) n = 1.f;
            float r = 1.f / n;
            featsh[e * 268 + 256 + a * 3 + 0] = vx * r;
            featsh[e * 268 + 256 + a * 3 + 1] = vy * r;
            featsh[e * 268 + 256 + a * 3 + 2] = vz * r;
        }
        __syncthreads();

        // GEMM + layernorm: each group handles 16 edges, 4 at a time
        int gbase = g * 16;
        for (int sb = 0; sb < 4; sb++) {
            int le = gbase + sb * 4;
            const float4* Wq = (const float4*)Wsh;
            const float4* f0 = (const float4*)&featsh[(le + 0) * 268];
            const float4* f1 = (const float4*)&featsh[(le + 1) * 268];
            const float4* f2 = (const float4*)&featsh[(le + 2) * 268];
            const float4* f3 = (const float4*)&featsh[(le + 3) * 268];
            float a0 = ebv, a1 = ebv, a2 = ebv, a3 = ebv;
            #pragma unroll 4
            for (int f4 = 0; f4 < 67; f4++) {
                float4 w = Wq[f4 * 128 + o];
                float4 q0 = f0[f4];
                a0 += w.x * q0.x; a0 += w.y * q0.y; a0 += w.z * q0.z; a0 += w.w * q0.w;
                float4 q1 = f1[f4];
                a1 += w.x * q1.x; a1 += w.y * q1.y; a1 += w.z * q1.z; a1 += w.w * q1.w;
                float4 q2 = f2[f4];
                a2 += w.x * q2.x; a2 += w.y * q2.y; a2 += w.z * q2.z; a2 += w.w * q2.w;
                float4 q3 = f3[f4];
                a3 += w.x * q3.x; a3 += w.y * q3.y; a3 += w.z * q3.z; a3 += w.w * q3.w;
            }

            // layernorm over the 128 outputs of each edge (128-thread group)
            float s0 = a0, s1 = a1, s2 = a2, s3 = a3;
            float p0 = a0 * a0, p1 = a1 * a1, p2 = a2 * a2, p3 = a3 * a3;
            #pragma unroll
            for (int off = 16; off; off >>= 1) {
                s0 += __shfl_down_sync(0xffffffffu, s0, off);
                s1 += __shfl_down_sync(0xffffffffu, s1, off);
                s2 += __shfl_down_sync(0xffffffffu, s2, off);
                s3 += __shfl_down_sync(0xffffffffu, s3, off);
                p0 += __shfl_down_sync(0xffffffffu, p0, off);
                p1 += __shfl_down_sync(0xffffffffu, p1, off);
                p2 += __shfl_down_sync(0xffffffffu, p2, off);
                p3 += __shfl_down_sync(0xffffffffu, p3, off);
            }
            int wg = (t >> 5) & 3;
            if ((t & 31) == 0) {
                float* rr = &red[g * 32 + wg * 8];
                rr[0] = s0; rr[1] = s1; rr[2] = s2; rr[3] = s3;
                rr[4] = p0; rr[5] = p1; rr[6] = p2; rr[7] = p3;
            }
            __syncthreads();
            float S0 = 0, S1 = 0, S2 = 0, S3 = 0, P0 = 0, P1 = 0, P2 = 0, P3 = 0;
            #pragma unroll
            for (int w = 0; w < 4; w++) {
                const float* rr = &red[g * 32 + w * 8];
                S0 += rr[0]; S1 += rr[1]; S2 += rr[2]; S3 += rr[3];
                P0 += rr[4]; P1 += rr[5]; P2 += rr[6]; P3 += rr[7];
            }
            if (e0 + le + 0 < E) {
                float mu = S0 * (1.f / 128.f);
                float sg = sqrtf((P0 - S0 * mu) * (1.f / 127.f) + 1e-6f);
                out[(size_t)(e0 + le + 0) * 128 + o] = egv * (a0 - mu) / (sg + 1e-6f) + ebi;
            }
            if (e0 + le + 1 < E) {
                float mu = S1 * (1.f / 128.f);
                float sg = sqrtf((P1 - S1 * mu) * (1.f / 127.f) + 1e-6f);
                out[(size_t)(e0 + le + 1) * 128 + o] = egv * (a1 - mu) / (sg + 1e-6f) + ebi;
            }
            if (e0 + le + 2 < E) {
                float mu = S2 * (1.f / 128.f);
                float sg = sqrtf((P2 - S2 * mu) * (1.f / 127.f) + 1e-6f);
                out[(size_t)(e0 + le + 2) * 128 + o] = egv * (a2 - mu) / (sg + 1e-6f) + ebi;
            }
            if (e0 + le + 3 < E) {
                float mu = S3 * (1.f / 128.f);
                float sg = sqrtf((P3 - S3 * mu) * (1.f / 127.f) + 1e-6f);
                out[(size_t)(e0 + le + 3) * 128 + o] = egv * (a3 - mu) / (sg + 1e-6f) + ebi;
            }
            __syncthreads();   // red reuse
        }
    }
}

// ------------------------------- launcher ----------------------------------
extern "C" void kernel_launch(void* const* d_in, const int* in_sizes, int n_in,
                              void* d_out, int out_size)
{
    const float* X   = (const float*)d_in[0];
    const int*   Ein = (const int*)d_in[1];
    const int*   Eex = (const int*)d_in[2];
    const float* nW  = (const float*)d_in[3];
    const float* nb  = (const float*)d_in[4];
    const float* eW  = (const float*)d_in[5];
    const float* eb  = (const float*)d_in[6];
    const float* gn  = (const float*)d_in[7];
    const float* bn  = (const float*)d_in[8];
    const float* ge  = (const float*)d_in[9];
    const float* be  = (const float*)d_in[10];

    int N = in_sizes[0] / 12;
    int E = in_sizes[1] / 2;
    float* out = (float*)d_out;

    cudaFuncSetAttribute(node_kernel, cudaFuncAttributeMaxDynamicSharedMemorySize,
                         NODE_SMEM_FLOATS * 4);
    cudaFuncSetAttribute(edge_kernel, cudaFuncAttributeMaxDynamicSharedMemorySize,
                         EDGE_SMEM_FLOATS * 4);

    int sms = 148;
    cudaDeviceGetAttribute(&sms, cudaDevAttrMultiProcessorCount, 0);

    q_kernel<<<(N + 127) / 128, 128>>>(X, N);
    node_kernel<<<512, 128, NODE_SMEM_FLOATS * 4>>>(X, nW, nb, gn, bn, out, N);

    float* out_in = out + (size_t)N * 128;
    float* out_ex = out_in + (size_t)E * 128;
    edge_kernel<<<sms, EK_THREADS, EDGE_SMEM_FLOATS * 4>>>(X, Ein, E, eW, eb, ge, be, out_in);
    edge_kernel<<<sms, EK_THREADS, EDGE_SMEM_FLOATS * 4>>>(X, Eex, E, eW, eb, ge, be, out_ex);
}

// round 3
// speedup vs baseline: 5.2353x; 5.2353x over previous
#include <cuda_runtime.h>
#include <cuda_bf16.h>
#include <cstdint>

// ===========================================================================
// Protein graph featurization.
//   h_V    = LN(node_rbf(96) @ node_W^T + node_b)        [N,128]
//   h_E_*  = LN(edge_feats(268) @ edge_W^T + edge_b)     [E,128] x2
// Edge GEMM on HMMA (mma.sync m16n8k16 bf16, 3-pass hi/lo split = fp32-grade).
// ===========================================================================

#define QMAX 131072
__device__ float g_Q[QMAX * 9];   // per-node frame: b1(3), n0(3), b2(3)

__device__ __constant__ int c_NA[6]  = {1, 1, 1, 0, 0, 3};
__device__ __constant__ int c_NB[6]  = {0, 2, 3, 2, 3, 2};
__device__ __constant__ int c_EA[16] = {1,1,2,1,0,1,3,2,2,0,2,3,0,0,3,3};
__device__ __constant__ int c_EB[16] = {1,2,1,0,1,3,1,2,0,2,3,2,0,3,0,3};
__device__ __constant__ int c_AMAP[4] = {1, 0, 2, 3};

// ------------------------------ helpers ------------------------------------
__device__ __forceinline__ uint32_t smem_to_u32(const void* p) {
    uint32_t a;
    asm("{ .reg .u64 t; cvta.to.shared.u64 t, %1; cvt.u32.u64 %0, t; }"
        : "=r"(a) : "l"(p));
    return a;
}
__device__ __forceinline__ void ldsm4(uint32_t* r, uint32_t addr) {
    asm volatile("ldmatrix.sync.aligned.m8n8.x4.shared.b16 {%0,%1,%2,%3}, [%4];"
        : "=r"(r[0]), "=r"(r[1]), "=r"(r[2]), "=r"(r[3]) : "r"(addr));
}
__device__ __forceinline__ void mma_bf16(float* d, const uint32_t* a,
                                         uint32_t b0, uint32_t b1) {
    asm volatile("mma.sync.aligned.m16n8k16.row.col.f32.bf16.bf16.f32 "
        "{%0,%1,%2,%3}, {%4,%5,%6,%7}, {%8,%9}, {%0,%1,%2,%3};"
        : "+f"(d[0]), "+f"(d[1]), "+f"(d[2]), "+f"(d[3])
        : "r"(a[0]), "r"(a[1]), "r"(a[2]), "r"(a[3]), "r"(b0), "r"(b1));
}
__device__ __forceinline__ uint32_t pk2(float a, float b) {
    uint32_t lo = __bfloat16_as_ushort(__float2bfloat16(a));
    uint32_t hi = __bfloat16_as_ushort(__float2bfloat16(b));
    return (hi << 16) | lo;
}
__device__ __forceinline__ float bfres(float x) {   // x - bf16(x)
    return x - __bfloat162float(__float2bfloat16(x));
}

// --------------------------- frame precompute ------------------------------
__global__ void q_kernel(const float* __restrict__ X, int N) {
    int i = blockIdx.x * blockDim.x + threadIdx.x;
    if (i >= N) return;
    float* q = &g_Q[i * 9];
    if (i == N - 1) {
        #pragma unroll
        for (int j = 0; j < 9; j++) q[j] = 0.f;
        return;
    }
    const float* x = X + (size_t)i * 12;
    float ax = x[3] - x[0], ay = x[4] - x[1], az = x[5] - x[2];
    float n = sqrtf(ax*ax + ay*ay + az*az); if (n == 0.f) n = 1.f;
    float r = 1.f / n;
    float u0x = ax*r, u0y = ay*r, u0z = az*r;
    float bx = x[6] - x[3], by = x[7] - x[4], bz = x[8] - x[5];
    n = sqrtf(bx*bx + by*by + bz*bz); if (n == 0.f) n = 1.f;
    r = 1.f / n;
    float u1x = bx*r, u1y = by*r, u1z = bz*r;
    float cx = u0y*u1z - u0z*u1y, cy = u0z*u1x - u0x*u1z, cz = u0x*u1y - u0y*u1x;
    n = sqrtf(cx*cx + cy*cy + cz*cz); if (n == 0.f) n = 1.f;
    r = 1.f / n;
    float n0x = cx*r, n0y = cy*r, n0z = cz*r;
    float dx = u0x-u1x, dy = u0y-u1y, dz = u0z-u1z;
    n = sqrtf(dx*dx + dy*dy + dz*dz); if (n == 0.f) n = 1.f;
    r = 1.f / n;
    float b1x = dx*r, b1y = dy*r, b1z = dz*r;
    q[0]=b1x; q[1]=b1y; q[2]=b1z;
    q[3]=n0x; q[4]=n0y; q[5]=n0z;
    q[6]=b1y*n0z-b1z*n0y; q[7]=b1z*n0x-b1x*n0z; q[8]=b1x*n0y-b1y*n0x;
}

// ------------------------------ node kernel --------------------------------
#define NODE_SMEM_FLOATS (96 * 128 + 96 + 12 + 8)
__global__ __launch_bounds__(128) void node_kernel(
    const float* __restrict__ X, const float* __restrict__ W,
    const float* __restrict__ b, const float* __restrict__ gain,
    const float* __restrict__ bias, float* __restrict__ out, int N)
{
    extern __shared__ float sm[];
    float* Wsh  = sm;
    float* feat = Wsh + 96 * 128;
    float* xsh  = feat + 96;
    float* red  = xsh + 12;
    int t = threadIdx.x;
    for (int i = t; i < 96 * 128; i += 128) {
        int o = i / 96, f = i - o * 96;
        Wsh[f * 128 + o] = W[i];
    }
    float nb = b[t], ng = gain[t], nbi = bias[t];
    __syncthreads();
    for (int i = blockIdx.x; i < N; i += gridDim.x) {
        if (t < 12) xsh[t] = X[(size_t)i * 12 + t];
        __syncthreads();
        if (t < 96) {
            int p = t >> 4, k = t & 15;
            int a = c_NA[p], bb = c_NB[p];
            float dx = xsh[a*3+0]-xsh[bb*3+0], dy = xsh[a*3+1]-xsh[bb*3+1], dz = xsh[a*3+2]-xsh[bb*3+2];
            float D = sqrtf(dx*dx + dy*dy + dz*dz + 1e-6f);
            float z = (D - (float)k * (20.f/15.f)) * 0.8f;
            feat[t] = __expf(-z * z);
        }
        __syncthreads();
        float acc = nb;
        #pragma unroll 8
        for (int f = 0; f < 96; f++) acc += feat[f] * Wsh[f * 128 + t];
        float s = acc, sq = acc * acc;
        #pragma unroll
        for (int off = 16; off; off >>= 1) {
            s  += __shfl_down_sync(0xffffffffu, s, off);
            sq += __shfl_down_sync(0xffffffffu, sq, off);
        }
        if ((t & 31) == 0) { red[(t>>5)*2] = s; red[(t>>5)*2+1] = sq; }
        __syncthreads();
        float S  = red[0]+red[2]+red[4]+red[6];
        float Sq = red[1]+red[3]+red[5]+red[7];
        float mu = S * (1.f/128.f);
        float sig = sqrtf((Sq - S*mu) * (1.f/127.f) + 1e-6f);
        out[(size_t)i * 128 + t] = ng * (acc - mu) / (sig + 1e-6f) + nbi;
        __syncthreads();
    }
}

// ---------------------------- edge HMMA kernel -----------------------------
// 256 thr (8 warps), 1 CTA/SM. Tile = 64 edges.
// Warp w: edges 16*(w&3)..+15, outputs 64*(w>>2)..+63.
// D[64,128] = feat[64,288] @ W[128,288]^T, 3x bf16 hi/lo passes.
// SMEM rows padded to 296 bf16 (592B = 37*16B; 37 mod 8 = 5 -> ldmatrix
// conflict-free).
#define KPAD      296
#define ROWB      592           // KPAD*2 bytes
#define OFF_PAR   0             // eb/gain/bias: 3*128 floats = 1536B
#define OFF_RED   1536          // 64 edges x 2 halves x float2 = 1024B
#define OFF_BHI   2560
#define OFF_BLO   (OFF_BHI + 128*ROWB)          // 78336
#define OFF_AHI   (OFF_BLO + 128*ROWB)          // 154112
#define OFF_ALO   (OFF_AHI + 64*ROWB)           // 192000
#define EDGE_SMEM (OFF_ALO + 64*ROWB)           // 229888

__global__ __launch_bounds__(256, 1)
void edge_hmma_kernel(const float* __restrict__ X, const int* __restrict__ idx,
                      int E, const float* __restrict__ W,
                      const float* __restrict__ eb, const float* __restrict__ egain,
                      const float* __restrict__ ebias, float* __restrict__ out)
{
    extern __shared__ char smem[];
    uint32_t sb = smem_to_u32(smem);
    int t = threadIdx.x;
    int wid = t >> 5, lane = t & 31;
    int egrp = wid & 3, nhalf = wid >> 2;
    int t4 = lane & 3, g = lane >> 2;

    // ---- one-time: params, W -> bf16 hi/lo in SMEM ----
    if (t < 128) {
        ((float*)(smem + OFF_PAR))[t]       = eb[t];
        ((float*)(smem + OFF_PAR))[128 + t] = egain[t];
        ((float*)(smem + OFF_PAR))[256 + t] = ebias[t];
    }
    for (int i = t; i < 128 * 268; i += 256) {
        int r = i / 268, k = i - r * 268;
        float w = W[i];
        float hi = __bfloat162float(__float2bfloat16(w));
        *(uint16_t*)(smem + OFF_BHI + r*ROWB + k*2) =
            __bfloat16_as_ushort(__float2bfloat16(w));
        *(uint16_t*)(smem + OFF_BLO + r*ROWB + k*2) =
            __bfloat16_as_ushort(__float2bfloat16(w - hi));
    }
    for (int i = t; i < 128 * 4; i += 256) {       // zero W cols 268..271
        int r = i >> 2, c = 268 + (i & 3);
        *(uint16_t*)(smem + OFF_BHI + r*ROWB + c*2) = 0;
        *(uint16_t*)(smem + OFF_BLO + r*ROWB + c*2) = 0;
    }
    __syncthreads();

    // ldmatrix lane address bases (k-offset added per step)
    uint32_t aOff = (uint32_t)(egrp*16 + (lane & 15)) * ROWB + ((lane & 16) ? 16u : 0u);
    uint32_t bRow = (uint32_t)(nhalf*64 + ((lane & 7) | ((lane & 16) >> 1)));
    uint32_t bOff = bRow * ROWB + ((lane & 8) ? 16u : 0u);
    uint32_t aHiB = sb + OFF_AHI + aOff, aLoB = sb + OFF_ALO + aOff;
    uint32_t bHiB = sb + OFF_BHI + bOff, bLoB = sb + OFF_BLO + bOff;

    int ntiles = (E + 63) >> 6;
    for (int tile = blockIdx.x; tile < ntiles; tile += gridDim.x) {
        int ebase = tile * 64;

        // ---- featgen: RBF (16 pairs x 16 rbf) ----
        #pragma unroll
        for (int it = 0; it < 4; it++) {
            int u = t + it * 256;
            int el = u >> 4, p = u & 15;
            int ge = ebase + el;
            if (ge < E) {
                int s = idx[ge], d2 = idx[E + ge];
                const float* xa = X + (size_t)s  * 12 + c_EA[p] * 3;
                const float* xb = X + (size_t)d2 * 12 + c_EB[p] * 3;
                float dx = xa[0]-xb[0], dy = xa[1]-xb[1], dz = xa[2]-xb[2];
                float D = sqrtf(dx*dx + dy*dy + dz*dz + 1e-6f);
                float f[16];
                #pragma unroll
                for (int k = 0; k < 16; k++) {
                    float z = (D - (float)k * (20.f/15.f)) * 0.8f;
                    f[k] = __expf(-z * z);
                }
                uint32_t hw[8], lw[8];
                #pragma unroll
                for (int k = 0; k < 8; k++) {
                    hw[k] = pk2(f[2*k], f[2*k+1]);
                    lw[k] = pk2(bfres(f[2*k]), bfres(f[2*k+1]));
                }
                char* ah = smem + OFF_AHI + el*ROWB + p*32;
                char* al = smem + OFF_ALO + el*ROWB + p*32;
                *(uint4*)(ah)      = make_uint4(hw[0],hw[1],hw[2],hw[3]);
                *(uint4*)(ah + 16) = make_uint4(hw[4],hw[5],hw[6],hw[7]);
                *(uint4*)(al)      = make_uint4(lw[0],lw[1],lw[2],lw[3]);
                *(uint4*)(al + 16) = make_uint4(lw[4],lw[5],lw[6],lw[7]);
            }
        }
        // ---- featgen: orientation (cols 256..267, zeros 268..271) ----
        if (t < 64) {
            int el = t, ge = ebase + el;
            if (ge < E) {
                int s = idx[ge], d2 = idx[E + ge];
                const float* xs_ = X + (size_t)s  * 12;
                const float* xd_ = X + (size_t)d2 * 12;
                float ox = xs_[0], oy = xs_[1], oz = xs_[2];
                const float* q = g_Q + (size_t)s * 9;
                float q0=q[0],q1=q[1],q2=q[2],q3=q[3],q4=q[4],q5=q[5],q6=q[6],q7=q[7],q8=q[8];
                float fv[12];
                #pragma unroll
                for (int a = 0; a < 4; a++) {
                    int da = c_AMAP[a];
                    float px = xd_[da*3+0]-ox, py = xd_[da*3+1]-oy, pz = xd_[da*3+2]-oz;
                    float vx = q0*px + q3*py + q6*pz;
                    float vy = q1*px + q4*py + q7*pz;
                    float vz = q2*px + q5*py + q8*pz;
                    float n = sqrtf(vx*vx + vy*vy + vz*vz);
                    if (n == 0.f) n = 1.f;
                    float r = 1.f / n;
                    fv[a*3+0] = vx*r; fv[a*3+1] = vy*r; fv[a*3+2] = vz*r;
                }
                uint32_t hw[8], lw[8];
                #pragma unroll
                for (int k = 0; k < 6; k++) {
                    hw[k] = pk2(fv[2*k], fv[2*k+1]);
                    lw[k] = pk2(bfres(fv[2*k]), bfres(fv[2*k+1]));
                }
                hw[6] = hw[7] = lw[6] = lw[7] = 0u;
                char* ah = smem + OFF_AHI + el*ROWB + 512;
                char* al = smem + OFF_ALO + el*ROWB + 512;
                *(uint4*)(ah)      = make_uint4(hw[0],hw[1],hw[2],hw[3]);
                *(uint4*)(ah + 16) = make_uint4(hw[4],hw[5],hw[6],hw[7]);
                *(uint4*)(al)      = make_uint4(lw[0],lw[1],lw[2],lw[3]);
                *(uint4*)(al + 16) = make_uint4(lw[4],lw[5],lw[6],lw[7]);
            }
        }
        __syncthreads();

        // ---- 3-pass HMMA: D += Ah*Bh + Al*Bh + Ah*Bl ----
        float acc[8][4];
        #pragma unroll
        for (int n = 0; n < 8; n++) { acc[n][0]=0; acc[n][1]=0; acc[n][2]=0; acc[n][3]=0; }

        #pragma unroll 1
        for (int s = 0; s < 17; s++) {
            uint32_t koff = (uint32_t)s * 32;
            uint32_t aH[4], aL[4], bF[4][4];
            ldsm4(aH, aHiB + koff);
            ldsm4(aL, aLoB + koff);
            #pragma unroll
            for (int np = 0; np < 4; np++) ldsm4(bF[np], bHiB + np*(16*ROWB) + koff);
            #pragma unroll
            for (int n = 0; n < 8; n++)
                mma_bf16(acc[n], aH, bF[n>>1][(n&1)*2], bF[n>>1][(n&1)*2+1]);
            #pragma unroll
            for (int n = 0; n < 8; n++)
                mma_bf16(acc[n], aL, bF[n>>1][(n&1)*2], bF[n>>1][(n&1)*2+1]);
            #pragma unroll
            for (int np = 0; np < 4; np++) ldsm4(bF[np], bLoB + np*(16*ROWB) + koff);
            #pragma unroll
            for (int n = 0; n < 8; n++)
                mma_bf16(acc[n], aH, bF[n>>1][(n&1)*2], bF[n>>1][(n&1)*2+1]);
        }
        __syncthreads();   // all warps done reading A

        // ---- epilogue: bias add + cross-half LN + store ----
        int e_lo = egrp*16 + g, e_hi = e_lo + 8;
        float S0=0, Q0=0, S1=0, Q1=0;
        #pragma unroll
        for (int n = 0; n < 8; n++) {
            int col = nhalf*64 + n*8 + t4*2;
            float2 e2 = *(const float2*)(smem + OFF_PAR + col*4);
            acc[n][0] += e2.x; acc[n][1] += e2.y;
            acc[n][2] += e2.x; acc[n][3] += e2.y;
            S0 += acc[n][0] + acc[n][1]; Q0 += acc[n][0]*acc[n][0] + acc[n][1]*acc[n][1];
            S1 += acc[n][2] + acc[n][3]; Q1 += acc[n][2]*acc[n][2] + acc[n][3]*acc[n][3];
        }
        #pragma unroll
        for (int off = 1; off <= 2; off <<= 1) {
            S0 += __shfl_xor_sync(0xffffffffu, S0, off);
            Q0 += __shfl_xor_sync(0xffffffffu, Q0, off);
            S1 += __shfl_xor_sync(0xffffffffu, S1, off);
            Q1 += __shfl_xor_sync(0xffffffffu, Q1, off);
        }
        float2* red = (float2*)(smem + OFF_RED);
        if (t4 == 0) {
            red[e_lo*2 + nhalf] = make_float2(S0, Q0);
            red[e_hi*2 + nhalf] = make_float2(S1, Q1);
        }
        __syncthreads();
        float2 ra = red[e_lo*2], rb = red[e_lo*2+1];
        float St0 = ra.x + rb.x, Qt0 = ra.y + rb.y;
        float2 rc = red[e_hi*2], rd = red[e_hi*2+1];
        float St1 = rc.x + rd.x, Qt1 = rc.y + rd.y;
        float mu0 = St0 * (1.f/128.f);
        float rs0 = 1.f / (sqrtf((Qt0 - St0*mu0) * (1.f/127.f) + 1e-6f) + 1e-6f);
        float mu1 = St1 * (1.f/128.f);
        float rs1 = 1.f / (sqrtf((Qt1 - St1*mu1) * (1.f/127.f) + 1e-6f) + 1e-6f);

        int ge_lo = ebase + e_lo, ge_hi = ebase + e_hi;
        #pragma unroll
        for (int n = 0; n < 8; n++) {
            int col = nhalf*64 + n*8 + t4*2;
            float2 gn = *(const float2*)(smem + OFF_PAR + 512 + col*4);
            float2 bs = *(const float2*)(smem + OFF_PAR + 1024 + col*4);
            if (ge_lo < E) {
                float2 o2;
                o2.x = gn.x * (acc[n][0] - mu0) * rs0 + bs.x;
                o2.y = gn.y * (acc[n][1] - mu0) * rs0 + bs.y;
                *(float2*)(out + (size_t)ge_lo*128 + col) = o2;
            }
            if (ge_hi < E) {
                float2 o2;
                o2.x = gn.x * (acc[n][2] - mu1) * rs1 + bs.x;
                o2.y = gn.y * (acc[n][3] - mu1) * rs1 + bs.y;
                *(float2*)(out + (size_t)ge_hi*128 + col) = o2;
            }
        }
        __syncthreads();   // red reuse next tile
    }
}

// ------------------------------- launcher ----------------------------------
extern "C" void kernel_launch(void* const* d_in, const int* in_sizes, int n_in,
                              void* d_out, int out_size)
{
    const float* X   = (const float*)d_in[0];
    const int*   Ein = (const int*)d_in[1];
    const int*   Eex = (const int*)d_in[2];
    const float* nW  = (const float*)d_in[3];
    const float* nb  = (const float*)d_in[4];
    const float* eW  = (const float*)d_in[5];
    const float* eb  = (const float*)d_in[6];
    const float* gn  = (const float*)d_in[7];
    const float* bn  = (const float*)d_in[8];
    const float* ge  = (const float*)d_in[9];
    const float* be  = (const float*)d_in[10];

    int N = in_sizes[0] / 12;
    int E = in_sizes[1] / 2;
    float* out = (float*)d_out;

    cudaFuncSetAttribute(node_kernel, cudaFuncAttributeMaxDynamicSharedMemorySize,
                         NODE_SMEM_FLOATS * 4);
    cudaFuncSetAttribute(edge_hmma_kernel, cudaFuncAttributeMaxDynamicSharedMemorySize,
                         EDGE_SMEM);

    int sms = 148;
    cudaDeviceGetAttribute(&sms, cudaDevAttrMultiProcessorCount, 0);

    q_kernel<<<(N + 127) / 128, 128>>>(X, N);
    node_kernel<<<512, 128, NODE_SMEM_FLOATS * 4>>>(X, nW, nb, gn, bn, out, N);

    float* out_in = out + (size_t)N * 128;
    float* out_ex = out_in + (size_t)E * 128;
    edge_hmma_kernel<<<sms, 256, EDGE_SMEM>>>(X, Ein, E, eW, eb, ge, be, out_in);
    edge_hmma_kernel<<<sms, 256, EDGE_SMEM>>>(X, Eex, E, eW, eb, ge, be, out_ex);
}

// round 6
// speedup vs baseline: 6.6197x; 1.2644x over previous
#include <cuda_runtime.h>
#include <cuda_bf16.h>
#include <cstdint>

// ===========================================================================
// Protein graph featurization.
//   h_V    = LN(node_rbf(96) @ node_W^T + node_b)        [N,128]
//   h_E_*  = LN(edge_feats(268) @ edge_W^T + edge_b)     [E,128] x2
// Edge GEMM on HMMA (mma.sync m16n8k16 bf16, 3-pass hi/lo = fp32-grade),
// warp-specialized producer/consumer with double-buffered A tiles.
// ===========================================================================

#define QMAX 131072
__device__ float g_Q[QMAX * 9];   // per-node frame: b1(3), n0(3), b2(3)

__device__ __constant__ int c_NA[6]  = {1, 1, 1, 0, 0, 3};
__device__ __constant__ int c_NB[6]  = {0, 2, 3, 2, 3, 2};
__device__ __constant__ int c_EA[16] = {1,1,2,1,0,1,3,2,2,0,2,3,0,0,3,3};
__device__ __constant__ int c_EB[16] = {1,2,1,0,1,3,1,2,0,2,3,2,0,3,0,3};
__device__ __constant__ int c_AMAP[4] = {1, 0, 2, 3};

// ------------------------------ helpers ------------------------------------
__device__ __forceinline__ uint32_t smem_to_u32(const void* p) {
    uint32_t a;
    asm("{ .reg .u64 t; cvta.to.shared.u64 t, %1; cvt.u32.u64 %0, t; }"
        : "=r"(a) : "l"(p));
    return a;
}
__device__ __forceinline__ void ldsm4(uint32_t* r, uint32_t addr) {
    asm volatile("ldmatrix.sync.aligned.m8n8.x4.shared.b16 {%0,%1,%2,%3}, [%4];"
        : "=r"(r[0]), "=r"(r[1]), "=r"(r[2]), "=r"(r[3]) : "r"(addr));
}
__device__ __forceinline__ void mma_bf16(float* d, const uint32_t* a,
                                         uint32_t b0, uint32_t b1) {
    asm volatile("mma.sync.aligned.m16n8k16.row.col.f32.bf16.bf16.f32 "
        "{%0,%1,%2,%3}, {%4,%5,%6,%7}, {%8,%9}, {%0,%1,%2,%3};"
        : "+f"(d[0]), "+f"(d[1]), "+f"(d[2]), "+f"(d[3])
        : "r"(a[0]), "r"(a[1]), "r"(a[2]), "r"(a[3]), "r"(b0), "r"(b1));
}
#define BAR_SYNC(id, cnt) \
    asm volatile("bar.sync %0, %1;" :: "r"(id), "r"(cnt) : "memory")
#define BAR_ARRIVE(id, cnt) \
    asm volatile("bar.arrive %0, %1;" :: "r"(id), "r"(cnt) : "memory")

__device__ __forceinline__ uint32_t pk2(float a, float b) {
    uint32_t lo = __bfloat16_as_ushort(__float2bfloat16(a));
    uint32_t hi = __bfloat16_as_ushort(__float2bfloat16(b));
    return (hi << 16) | lo;
}
__device__ __forceinline__ float bfres(float x) {   // x - bf16(x)
    return x - __bfloat162float(__float2bfloat16(x));
}

// --------------------------- frame precompute ------------------------------
__global__ void q_kernel(const float* __restrict__ X, int N) {
    int i = blockIdx.x * blockDim.x + threadIdx.x;
    if (i >= N) return;
    float* q = &g_Q[i * 9];
    if (i == N - 1) {
        #pragma unroll
        for (int j = 0; j < 9; j++) q[j] = 0.f;
        return;
    }
    const float* x = X + (size_t)i * 12;
    float ax = x[3] - x[0], ay = x[4] - x[1], az = x[5] - x[2];
    float n = sqrtf(ax*ax + ay*ay + az*az); if (n == 0.f) n = 1.f;
    float r = 1.f / n;
    float u0x = ax*r, u0y = ay*r, u0z = az*r;
    float bx = x[6] - x[3], by = x[7] - x[4], bz = x[8] - x[5];
    n = sqrtf(bx*bx + by*by + bz*bz); if (n == 0.f) n = 1.f;
    r = 1.f / n;
    float u1x = bx*r, u1y = by*r, u1z = bz*r;
    float cx = u0y*u1z - u0z*u1y, cy = u0z*u1x - u0x*u1z, cz = u0x*u1y - u0y*u1x;
    n = sqrtf(cx*cx + cy*cy + cz*cz); if (n == 0.f) n = 1.f;
    r = 1.f / n;
    float n0x = cx*r, n0y = cy*r, n0z = cz*r;
    float dx = u0x-u1x, dy = u0y-u1y, dz = u0z-u1z;
    n = sqrtf(dx*dx + dy*dy + dz*dz); if (n == 0.f) n = 1.f;
    r = 1.f / n;
    float b1x = dx*r, b1y = dy*r, b1z = dz*r;
    q[0]=b1x; q[1]=b1y; q[2]=b1z;
    q[3]=n0x; q[4]=n0y; q[5]=n0z;
    q[6]=b1y*n0z-b1z*n0y; q[7]=b1z*n0x-b1x*n0z; q[8]=b1x*n0y-b1y*n0x;
}

// ------------------------------ node kernel --------------------------------
#define NODE_SMEM_FLOATS (96 * 128 + 96 + 12 + 8)
__global__ __launch_bounds__(128) void node_kernel(
    const float* __restrict__ X, const float* __restrict__ W,
    const float* __restrict__ b, const float* __restrict__ gain,
    const float* __restrict__ bias, float* __restrict__ out, int N)
{
    extern __shared__ float sm[];
    float* Wsh  = sm;
    float* feat = Wsh + 96 * 128;
    float* xsh  = feat + 96;
    float* red  = xsh + 12;
    int t = threadIdx.x;
    for (int i = t; i < 96 * 128; i += 128) {
        int o = i / 96, f = i - o * 96;
        Wsh[f * 128 + o] = W[i];
    }
    float nb = b[t], ng = gain[t], nbi = bias[t];
    __syncthreads();
    for (int i = blockIdx.x; i < N; i += gridDim.x) {
        if (t < 12) xsh[t] = X[(size_t)i * 12 + t];
        __syncthreads();
        if (t < 96) {
            int p = t >> 4, k = t & 15;
            int a = c_NA[p], bb = c_NB[p];
            float dx = xsh[a*3+0]-xsh[bb*3+0], dy = xsh[a*3+1]-xsh[bb*3+1], dz = xsh[a*3+2]-xsh[bb*3+2];
            float D = sqrtf(dx*dx + dy*dy + dz*dz + 1e-6f);
            float z = (D - (float)k * (20.f/15.f)) * 0.8f;
            feat[t] = __expf(-z * z);
        }
        __syncthreads();
        float acc = nb;
        #pragma unroll 8
        for (int f = 0; f < 96; f++) acc += feat[f] * Wsh[f * 128 + t];
        float s = acc, sq = acc * acc;
        #pragma unroll
        for (int off = 16; off; off >>= 1) {
            s  += __shfl_down_sync(0xffffffffu, s, off);
            sq += __shfl_down_sync(0xffffffffu, sq, off);
        }
        if ((t & 31) == 0) { red[(t>>5)*2] = s; red[(t>>5)*2+1] = sq; }
        __syncthreads();
        float S  = red[0]+red[2]+red[4]+red[6];
        float Sq = red[1]+red[3]+red[5]+red[7];
        float mu = S * (1.f/128.f);
        float sig = sqrtf((Sq - S*mu) * (1.f/127.f) + 1e-6f);
        out[(size_t)i * 128 + t] = ng * (acc - mu) / (sig + 1e-6f) + nbi;
        __syncthreads();
    }
}

// ---------------------- edge HMMA kernel (specialized) ---------------------
// 512 thr: warps 0-7 consumers (MMA m32n128 + LN + store),
//          warps 8-15 producers (featgen), A double-buffered, tile=32 edges.
// Row stride 560B = 35*16B (35 mod 8 = 3 -> ldmatrix conflict-free).
#define ROWB     560
#define OFF_PAR  0                          // eb/gain/bias: 1536 B
#define OFF_RED  1536                       // 32 edges x 4 quarters x float2
#define OFF_BHI  2560
#define OFF_BLO  (OFF_BHI + 128*ROWB)       // 74240
#define OFF_A    (OFF_BLO + 128*ROWB)       // 145920
#define A_HALF   (32*ROWB)                  // 17920
#define A_STAGE  (2*A_HALF)                 // 35840
#define EDGE_SMEM (OFF_A + 2*A_STAGE)       // 217600
// named barriers: 1,2 = full[s]; 3,4 = empty[s]; 5 = consumers; 6 = producers

__global__ __launch_bounds__(512, 1)
void edge_hmma_kernel(const float* __restrict__ X,
                      const int* __restrict__ idx1, const int* __restrict__ idx2,
                      int E, const float* __restrict__ W,
                      const float* __restrict__ eb, const float* __restrict__ egain,
                      const float* __restrict__ ebias,
                      float* __restrict__ out1, float* __restrict__ out2)
{
    extern __shared__ char smem[];
    uint32_t sb = smem_to_u32(smem);
    int t = threadIdx.x;

    // ---- one-time staging: params + W -> bf16 hi/lo ----
    if (t < 128) {
        ((float*)(smem + OFF_PAR))[t]       = eb[t];
        ((float*)(smem + OFF_PAR))[128 + t] = egain[t];
        ((float*)(smem + OFF_PAR))[256 + t] = ebias[t];
    }
    for (int i = t; i < 128 * 268; i += 512) {
        int r = i / 268, k = i - r * 268;
        float w = W[i];
        float hi = __bfloat162float(__float2bfloat16(w));
        *(uint16_t*)(smem + OFF_BHI + r*ROWB + k*2) =
            __bfloat16_as_ushort(__float2bfloat16(w));
        *(uint16_t*)(smem + OFF_BLO + r*ROWB + k*2) =
            __bfloat16_as_ushort(__float2bfloat16(w - hi));
    }
    for (int i = t; i < 128 * 4; i += 512) {       // zero W cols 268..271
        int r = i >> 2, c = 268 + (i & 3);
        *(uint16_t*)(smem + OFF_BHI + r*ROWB + c*2) = 0;
        *(uint16_t*)(smem + OFF_BLO + r*ROWB + c*2) = 0;
    }
    __syncthreads();

    int ntiles  = (E + 31) >> 5;
    int ntiles2 = ntiles * 2;

    if (t < 256) {
        // =========================== CONSUMER ===========================
        int wid = t >> 5, lane = t & 31;
        int egrp = wid & 1, nq = wid >> 1;
        int t4 = lane & 3, g = lane >> 2;
        uint32_t aOff = (uint32_t)(egrp*16 + (lane & 15)) * ROWB
                      + ((lane & 16) ? 16u : 0u);
        uint32_t bRow = (uint32_t)(nq*32 + (lane & 7) + ((lane & 16) >> 1));
        uint32_t bOff = bRow * ROWB + ((lane & 8) ? 16u : 0u);
        uint32_t bHi  = sb + OFF_BHI + bOff;
        uint32_t bLo  = sb + OFF_BLO + bOff;

        int i = 0;
        for (int tile = blockIdx.x; tile < ntiles2; tile += gridDim.x, i++) {
            int s = i & 1;
            bool ex = tile >= ntiles;
            int ebase = (ex ? tile - ntiles : tile) * 32;
            float* outp = ex ? out2 : out1;
            uint32_t aHi = sb + OFF_A + s*A_STAGE + aOff;
            uint32_t aLo = aHi + A_HALF;

            BAR_SYNC(1 + s, 512);                     // wait full

            float acc[4][4];
            #pragma unroll
            for (int n = 0; n < 4; n++)
                acc[n][0] = acc[n][1] = acc[n][2] = acc[n][3] = 0.f;

            #pragma unroll 1
            for (int ks = 0; ks < 17; ks++) {
                uint32_t ko = (uint32_t)ks * 32;
                uint32_t aH[4], aL[4], bH[2][4], bL[2][4];
                ldsm4(aH, aHi + ko);
                ldsm4(bH[0], bHi + ko);
                ldsm4(bH[1], bHi + 16*ROWB + ko);
                ldsm4(aL, aLo + ko);
                ldsm4(bL[0], bLo + ko);
                ldsm4(bL[1], bLo + 16*ROWB + ko);
                #pragma unroll
                for (int n = 0; n < 4; n++)
                    mma_bf16(acc[n], aH, bH[n>>1][(n&1)*2], bH[n>>1][(n&1)*2+1]);
                #pragma unroll
                for (int n = 0; n < 4; n++)
                    mma_bf16(acc[n], aL, bH[n>>1][(n&1)*2], bH[n>>1][(n&1)*2+1]);
                #pragma unroll
                for (int n = 0; n < 4; n++)
                    mma_bf16(acc[n], aH, bL[n>>1][(n&1)*2], bL[n>>1][(n&1)*2+1]);
            }
            BAR_ARRIVE(3 + s, 512);                   // signal empty

            // ---- epilogue: bias + LN + store ----
            int e0 = egrp*16 + g, e1 = e0 + 8;
            float S0=0, Q0=0, S1=0, Q1=0;
            #pragma unroll
            for (int n = 0; n < 4; n++) {
                int col = nq*32 + n*8 + t4*2;
                float2 b2 = *(const float2*)(smem + OFF_PAR + col*4);
                acc[n][0] += b2.x; acc[n][1] += b2.y;
                acc[n][2] += b2.x; acc[n][3] += b2.y;
                S0 += acc[n][0] + acc[n][1];
                Q0 += acc[n][0]*acc[n][0] + acc[n][1]*acc[n][1];
                S1 += acc[n][2] + acc[n][3];
                Q1 += acc[n][2]*acc[n][2] + acc[n][3]*acc[n][3];
            }
            #pragma unroll
            for (int off = 1; off <= 2; off <<= 1) {
                S0 += __shfl_xor_sync(0xffffffffu, S0, off);
                Q0 += __shfl_xor_sync(0xffffffffu, Q0, off);
                S1 += __shfl_xor_sync(0xffffffffu, S1, off);
                Q1 += __shfl_xor_sync(0xffffffffu, Q1, off);
            }
            float2* red = (float2*)(smem + OFF_RED);
            if (t4 == 0) {
                red[e0*4 + nq] = make_float2(S0, Q0);
                red[e1*4 + nq] = make_float2(S1, Q1);
            }
            BAR_SYNC(5, 256);
            float St0=0, Qt0=0, St1=0, Qt1=0;
            #pragma unroll
            for (int q = 0; q < 4; q++) {
                float2 r0 = red[e0*4 + q]; St0 += r0.x; Qt0 += r0.y;
                float2 r1 = red[e1*4 + q]; St1 += r1.x; Qt1 += r1.y;
            }
            float mu0 = St0 * (1.f/128.f);
            float rs0 = 1.f / (sqrtf((Qt0 - St0*mu0) * (1.f/127.f) + 1e-6f) + 1e-6f);
            float mu1 = St1 * (1.f/128.f);
            float rs1 = 1.f / (sqrtf((Qt1 - St1*mu1) * (1.f/127.f) + 1e-6f) + 1e-6f);

            int ge0 = ebase + e0, ge1 = ebase + e1;
            float* op0 = outp + (size_t)ge0 * 128;
            float* op1 = outp + (size_t)ge1 * 128;
            #pragma unroll
            for (int n = 0; n < 4; n++) {
                int col = nq*32 + n*8 + t4*2;
                float2 gn2 = *(const float2*)(smem + OFF_PAR + 512 + col*4);
                float2 bs2 = *(const float2*)(smem + OFF_PAR + 1024 + col*4);
                if (ge0 < E) {
                    float2 o;
                    o.x = gn2.x * (acc[n][0] - mu0) * rs0 + bs2.x;
                    o.y = gn2.y * (acc[n][1] - mu0) * rs0 + bs2.y;
                    __stcs((float2*)(op0 + col), o);
                }
                if (ge1 < E) {
                    float2 o;
                    o.x = gn2.x * (acc[n][2] - mu1) * rs1 + bs2.x;
                    o.y = gn2.y * (acc[n][3] - mu1) * rs1 + bs2.y;
                    __stcs((float2*)(op1 + col), o);
                }
            }
        }
    } else {
        // =========================== PRODUCER ===========================
        int t2 = t - 256;
        int el = t2 & 31;        // edge within tile
        int pbase = t2 >> 5;     // pair base 0..7 (handles pbase, pbase+8)

        int i = 0;
        for (int tile = blockIdx.x; tile < ntiles2; tile += gridDim.x, i++) {
            int s = i & 1;
            bool ex = tile >= ntiles;
            int ebase = (ex ? tile - ntiles : tile) * 32;
            const int* ix = ex ? idx2 : idx1;
            char* aHb = smem + OFF_A + s*A_STAGE;
            char* aLb = aHb + A_HALF;

            if (i >= 2) BAR_SYNC(3 + s, 512);         // wait empty

            int ge = ebase + el;
            if (ge < E) {
                int sidx = ix[ge], didx = ix[E + ge];
                const float* xs_ = X + (size_t)sidx * 12;
                const float* xd_ = X + (size_t)didx * 12;

                #pragma unroll
                for (int it = 0; it < 2; it++) {
                    int p = pbase + it * 8;
                    const float* xa = xs_ + c_EA[p] * 3;
                    const float* xb = xd_ + c_EB[p] * 3;
                    float dx = xa[0]-xb[0], dy = xa[1]-xb[1], dz = xa[2]-xb[2];
                    float D = sqrtf(dx*dx + dy*dy + dz*dz + 1e-6f);
                    float f[16];
                    #pragma unroll
                    for (int k = 0; k < 16; k++) {
                        float z = (D - (float)k * (20.f/15.f)) * 0.8f;
                        f[k] = __expf(-z * z);
                    }
                    uint32_t hw[8], lw[8];
                    #pragma unroll
                    for (int k = 0; k < 8; k++) {
                        hw[k] = pk2(f[2*k], f[2*k+1]);
                        lw[k] = pk2(bfres(f[2*k]), bfres(f[2*k+1]));
                    }
                    char* ah = aHb + el*ROWB + p*32;
                    char* al = aLb + el*ROWB + p*32;
                    *(uint4*)(ah)      = make_uint4(hw[0],hw[1],hw[2],hw[3]);
                    *(uint4*)(ah + 16) = make_uint4(hw[4],hw[5],hw[6],hw[7]);
                    *(uint4*)(al)      = make_uint4(lw[0],lw[1],lw[2],lw[3]);
                    *(uint4*)(al + 16) = make_uint4(lw[4],lw[5],lw[6],lw[7]);
                }

                if (t2 < 32) {   // orientation features, cols 256..271
                    float ox = xs_[0], oy = xs_[1], oz = xs_[2];
                    const float* q = g_Q + (size_t)sidx * 9;
                    float q0=q[0],q1=q[1],q2=q[2],q3=q[3],q4=q[4],
                          q5=q[5],q6=q[6],q7=q[7],q8=q[8];
                    float fv[12];
                    #pragma unroll
                    for (int a = 0; a < 4; a++) {
                        int da = c_AMAP[a];
                        float px = xd_[da*3+0]-ox, py = xd_[da*3+1]-oy, pz = xd_[da*3+2]-oz;
                        float vx = q0*px + q3*py + q6*pz;
                        float vy = q1*px + q4*py + q7*pz;
                        float vz = q2*px + q5*py + q8*pz;
                        float n = sqrtf(vx*vx + vy*vy + vz*vz);
                        if (n == 0.f) n = 1.f;
                        float r = 1.f / n;
                        fv[a*3+0] = vx*r; fv[a*3+1] = vy*r; fv[a*3+2] = vz*r;
                    }
                    uint32_t hw[8], lw[8];
                    #pragma unroll
                    for (int k = 0; k < 6; k++) {
                        hw[k] = pk2(fv[2*k], fv[2*k+1]);
                        lw[k] = pk2(bfres(fv[2*k]), bfres(fv[2*k+1]));
                    }
                    hw[6] = hw[7] = lw[6] = lw[7] = 0u;
                    char* ah = aHb + el*ROWB + 512;
                    char* al = aLb + el*ROWB + 512;
                    *(uint4*)(ah)      = make_uint4(hw[0],hw[1],hw[2],hw[3]);
                    *(uint4*)(ah + 16) = make_uint4(hw[4],hw[5],hw[6],hw[7]);
                    *(uint4*)(al)      = make_uint4(lw[0],lw[1],lw[2],lw[3]);
                    *(uint4*)(al + 16) = make_uint4(lw[4],lw[5],lw[6],lw[7]);
                }
            }
            BAR_SYNC(6, 256);        // drain producer STS (visibility)
            BAR_ARRIVE(1 + s, 512);  // signal full
        }
    }
}

// ------------------------------- launcher ----------------------------------
extern "C" void kernel_launch(void* const* d_in, const int* in_sizes, int n_in,
                              void* d_out, int out_size)
{
    const float* X   = (const float*)d_in[0];
    const int*   Ein = (const int*)d_in[1];
    const int*   Eex = (const int*)d_in[2];
    const float* nW  = (const float*)d_in[3];
    const float* nb  = (const float*)d_in[4];
    const float* eW  = (const float*)d_in[5];
    const float* eb  = (const float*)d_in[6];
    const float* gn  = (const float*)d_in[7];
    const float* bn  = (const float*)d_in[8];
    const float* ge  = (const float*)d_in[9];
    const float* be  = (const float*)d_in[10];

    int N = in_sizes[0] / 12;
    int E = in_sizes[1] / 2;
    float* out = (float*)d_out;

    cudaFuncSetAttribute(node_kernel, cudaFuncAttributeMaxDynamicSharedMemorySize,
                         NODE_SMEM_FLOATS * 4);
    cudaFuncSetAttribute(edge_hmma_kernel, cudaFuncAttributeMaxDynamicSharedMemorySize,
                         EDGE_SMEM);

    int sms = 148;
    cudaDeviceGetAttribute(&sms, cudaDevAttrMultiProcessorCount, 0);

    q_kernel<<<(N + 127) / 128, 128>>>(X, N);
    node_kernel<<<512, 128, NODE_SMEM_FLOATS * 4>>>(X, nW, nb, gn, bn, out, N);

    float* out_in = out + (size_t)N * 128;
    float* out_ex = out_in + (size_t)E * 128;
    edge_hmma_kernel<<<sms, 512, EDGE_SMEM>>>(X, Ein, Eex, E, eW, eb, ge, be,
                                              out_in, out_ex);
}